// round 11
// baseline (speedup 1.0000x reference)
#include <cuda_runtime.h>

// OriginNoiseBilateral R11: 17x17 bilateral, 8x3x512x512 fp32 NCHW.
// R8's winning structure (grid-launched, V=4 as 2 packed f32x2 pairs, 48x48
// float4 tile, smem dym row table, lb(256,3), mid unroll x2) with the weight
// exponentials evaluated via ONE ex2.approx.f16x2 per pair instead of two
// scalar f32 EX2s. Model: FMA and MUFU streams were co-loaded (~34 vs ~32
// SMSP-cyc/tap); this halves the MUFU stream. f32 arg chain unchanged.

namespace {
constexpr int H = 512, W = 512, C = 3;
constexpr int HW = H * W;
constexpr int RMAX = 8;
constexpr int BX = 32, BY = 8;        // 256 threads
constexpr int V  = 4;                 // vertical outputs per thread (2 pairs)
constexpr int TW = BX;                // 32-wide output tile
constexpr int TH = BY * V;            // 32-tall output tile
constexpr int SW = TW + 2 * RMAX;     // 48
constexpr int SH = TH + 2 * RMAX;     // 48
constexpr int NTAP = 2 * RMAX + 1;    // 17
constexpr int NROW = V + 2 * RMAX;    // 20
constexpr float NEG_BIG = -1e30f;
constexpr float LOG2E = 1.4426950408889634f;
}

typedef unsigned long long u64;
typedef unsigned int u32;

__device__ __forceinline__ float ex2f(float x) {
    float y;
    asm("ex2.approx.ftz.f32 %0, %1;" : "=f"(y) : "f"(x));
    return y;
}
__device__ __forceinline__ u64 pack2(float lo, float hi) {
    u64 r;
    asm("mov.b64 %0, {%1, %2};" : "=l"(r) : "f"(lo), "f"(hi));
    return r;
}
__device__ __forceinline__ void unpack2(u64 v, float& lo, float& hi) {
    asm("mov.b64 {%0, %1}, %2;" : "=f"(lo), "=f"(hi) : "l"(v));
}
__device__ __forceinline__ u64 fma2(u64 a, u64 b, u64 c) {
    u64 d;
    asm("fma.rn.f32x2 %0, %1, %2, %3;" : "=l"(d) : "l"(a), "l"(b), "l"(c));
    return d;
}
__device__ __forceinline__ u64 add2(u64 a, u64 b) {
    u64 d;
    asm("add.rn.f32x2 %0, %1, %2;" : "=l"(d) : "l"(a), "l"(b));
    return d;
}

// Packed exp2 of an f32x2 arg via fp16: cvt -> ex2.approx.f16x2 -> cvt back.
// args are <= 0; overflow (NEG_BIG) converts to -inf -> ex2 = 0 (mask ok).
__device__ __forceinline__ u64 ex2_pair(u64 arg) {
    float a0, a1;
    unpack2(arg, a0, a1);
    u32 h;
    asm("cvt.rn.f16x2.f32 %0, %1, %2;" : "=r"(h) : "f"(a1), "f"(a0)); // {hi:a1, lo:a0}
    u32 e;
    asm("ex2.approx.f16x2 %0, %1;" : "=r"(e) : "r"(h));
    float w0, w1;
    asm("{\n\t"
        ".reg .b16 lo, hi;\n\t"
        "mov.b32 {lo, hi}, %2;\n\t"
        "cvt.f32.f16 %0, lo;\n\t"
        "cvt.f32.f16 %1, hi;\n\t"
        "}" : "=f"(w0), "=f"(w1) : "r"(e));
    return pack2(w0, w1);
}

struct PairState {
    u64 ccx[2], ccy[2], ccz[2];   // packed A-scaled center rgb per pair
    u64 nx[2], ny[2], nz[2], dn[2];
};

// One halo row. dx^2 terms are compile-time FFMA immediates.
template<bool P01, bool P23>
__device__ __forceinline__ void process_row(const float4* __restrict__ row,
                                            float m /* -inv2s */,
                                            u64 rb0, u64 rb1, PairState& st)
{
    #pragma unroll
    for (int dx = 0; dx < NTAP; dx++) {
        float4 s = row[dx];
        const float d2 = (float)((dx - RMAX) * (dx - RMAX));
        float sw2 = fmaf(d2, m, s.w);          // FFMA-imm (rt=1)
        u64 sw22 = pack2(sw2, sw2);
        u64 sx2  = pack2(s.x, s.x);
        u64 sy2  = pack2(s.y, s.y);
        u64 sz2  = pack2(s.z, s.z);
        if (P01) {
            u64 arg = fma2(sz2, st.ccz[0],
                      fma2(sy2, st.ccy[0],
                      fma2(sx2, st.ccx[0], add2(sw22, rb0))));
            u64 w2 = ex2_pair(arg);
            st.nx[0] = fma2(w2, sx2, st.nx[0]);
            st.ny[0] = fma2(w2, sy2, st.ny[0]);
            st.nz[0] = fma2(w2, sz2, st.nz[0]);
            st.dn[0] = add2(st.dn[0], w2);
        }
        if (P23) {
            u64 arg = fma2(sz2, st.ccz[1],
                      fma2(sy2, st.ccy[1],
                      fma2(sx2, st.ccx[1], add2(sw22, rb1))));
            u64 w2 = ex2_pair(arg);
            st.nx[1] = fma2(w2, sx2, st.nx[1]);
            st.ny[1] = fma2(w2, sy2, st.ny[1]);
            st.nz[1] = fma2(w2, sz2, st.nz[1]);
            st.dn[1] = add2(st.dn[1], w2);
        }
    }
}

__global__ __launch_bounds__(256, 3)
void bilateral_kernel(const float* __restrict__ img,
                      const float* __restrict__ params,
                      float* __restrict__ out)
{
    __shared__ float4 tile[SH * SW];             // 36864 B
    __shared__ float  dym[NROW][V];              // thread-invariant row terms

    const int n   = blockIdx.z;
    const int tx  = threadIdx.x;
    const int ty  = threadIdx.y;
    const int tid = ty * BX + tx;

    const int x0 = blockIdx.x * TW - RMAX;
    const int y0 = blockIdx.y * TH - RMAX;

    const float* im = img + (size_t)n * C * HW;

    const int radius = ((((int)params[n * 3 + 0]) * 14 + 3) - 1) >> 1;
    const int r = radius < RMAX ? radius : RMAX;
    const float p1 = params[n * 3 + 1];
    const float p2 = params[n * 3 + 2];
    const float sc = fmaf(p1, 99.0f, 1.0f);
    const float ss = fmaf(p2, 99.0f, 1.0f);
    // 255^2 (reference pixel scaling) and log2(e) folded into constants.
    const float inv2c = 65025.0f * LOG2E / (2.0f * sc * sc);
    const float inv2s = LOG2E / (2.0f * ss * ss);
    const float m = -inv2s;
    const float A = 2.0f * inv2c;

    // Thread-invariant per-(row, v) spatial terms: dy^2*m, NEG_BIG if |dy|>8.
    if (tid < NROW * V) {
        int i = tid >> 2, v = tid & 3;
        int dy = i - RMAX - v;
        dym[i][v] = (dy >= -RMAX && dy <= RMAX)
                  ? ((float)(dy * dy)) * m : NEG_BIG;
    }

    // Halo load with edge clamp; .w = -inv2c * |rgb|^2.
    #pragma unroll
    for (int i = tid; i < SH * SW; i += BX * BY) {
        int sy = i / SW, sx = i % SW;
        int gy = min(max(y0 + sy, 0), H - 1);
        int gx = min(max(x0 + sx, 0), W - 1);
        int b  = gy * W + gx;
        float a0 = im[b], a1 = im[b + HW], a2 = im[b + 2 * HW];
        float sq = fmaf(a2, a2, fmaf(a1, a1, a0 * a0));
        tile[i] = make_float4(a0, a1, a2, -inv2c * sq);
    }
    __syncthreads();

    float* obase = out + (size_t)n * C * HW + blockIdx.x * TW + tx;
    const int oy0 = blockIdx.y * TH + ty * V;

    if (r == RMAX) {
        // ---------------- Hot path ----------------
        float4 cc[V];
        #pragma unroll
        for (int v = 0; v < V; v++)
            cc[v] = tile[(ty * V + v + RMAX) * SW + (tx + RMAX)];

        PairState st;
        #pragma unroll
        for (int p = 0; p < 2; p++) {
            st.ccx[p] = pack2(A * cc[2*p].x, A * cc[2*p+1].x);
            st.ccy[p] = pack2(A * cc[2*p].y, A * cc[2*p+1].y);
            st.ccz[p] = pack2(A * cc[2*p].z, A * cc[2*p+1].z);
            st.nx[p] = st.ny[p] = st.nz[p] = st.dn[p] = pack2(0.0f, 0.0f);
        }
        const u64 cw01 = pack2(cc[0].w, cc[1].w);
        const u64 cw23 = pack2(cc[2].w, cc[3].w);

        const float4* row = &tile[(ty * V) * SW + tx];

        // Head rows: only pair01 active (i = 0, 1).
        #pragma unroll
        for (int i = 0; i < 2; i++) {
            u64 rb0 = add2(cw01, *(const u64*)&dym[i][0]);
            process_row<true, false>(row, m, rb0, 0, st);
            row += SW;
        }
        // Mid rows: both pairs (i = 2..17).
        #pragma unroll 2
        for (int i = 2; i < 2 * RMAX + 2; i++) {
            u64 rb0 = add2(cw01, *(const u64*)&dym[i][0]);
            u64 rb1 = add2(cw23, *(const u64*)&dym[i][2]);
            process_row<true, true>(row, m, rb0, rb1, st);
            row += SW;
        }
        // Tail rows: only pair23 active (i = 18, 19).
        #pragma unroll
        for (int i = 2 * RMAX + 2; i < NROW; i++) {
            u64 rb1 = add2(cw23, *(const u64*)&dym[i][2]);
            process_row<false, true>(row, m, 0, rb1, st);
            row += SW;
        }

        #pragma unroll
        for (int p = 0; p < 2; p++) {
            float nxl, nxh, nyl, nyh, nzl, nzh, dl, dh;
            unpack2(st.nx[p], nxl, nxh);
            unpack2(st.ny[p], nyl, nyh);
            unpack2(st.nz[p], nzl, nzh);
            unpack2(st.dn[p], dl, dh);
            float il = __fdividef(1.0f, dl);
            float ih = __fdividef(1.0f, dh);
            float* o0 = obase + (oy0 + 2*p) * W;
            float* o1 = obase + (oy0 + 2*p + 1) * W;
            o0[0] = nxl * il;  o0[HW] = nyl * il;  o0[2*HW] = nzl * il;
            o1[0] = nxh * ih;  o1[HW] = nyh * ih;  o1[2*HW] = nzh * ih;
        }
    } else {
        // ---------------- Cold generic path (radius < 8) ----------------
        // Keeps full fp32 EX2 (precision-identical to reference path).
        #pragma unroll 1
        for (int v = 0; v < V; v++) {
            const float4 c = tile[(ty * V + v + RMAX) * SW + (tx + RMAX)];
            float n0 = 0.0f, n1 = 0.0f, n2 = 0.0f, den = 0.0f;
            #pragma unroll 1
            for (int dy = -r; dy <= r; dy++) {
                const float4* grow = &tile[(ty * V + v + RMAX + dy) * SW + (tx + RMAX)];
                const float spy = (float)(dy * dy);
                #pragma unroll 1
                for (int dx = -r; dx <= r; dx++) {
                    float4 s = grow[dx];
                    float tt = fmaf(s.z, c.z, fmaf(s.y, c.y, s.x * c.x));
                    float sp2 = spy + (float)(dx * dx);
                    float arg = fmaf(tt, A, fmaf(sp2, m, s.w + c.w));
                    float w = ex2f(arg);
                    n0 = fmaf(w, s.x, n0);
                    n1 = fmaf(w, s.y, n1);
                    n2 = fmaf(w, s.z, n2);
                    den += w;
                }
            }
            float inv = __fdividef(1.0f, den);
            float* o = obase + (oy0 + v) * W;
            o[0] = n0 * inv;  o[HW] = n1 * inv;  o[2*HW] = n2 * inv;
        }
    }
}

extern "C" void kernel_launch(void* const* d_in, const int* in_sizes, int n_in,
                              void* d_out, int out_size) {
    const float* img    = (const float*)d_in[0];
    const float* params = (const float*)d_in[1];
    float*       outp   = (float*)d_out;
    const int N = in_sizes[1] / 3;   // 8 images
    dim3 block(BX, BY, 1);
    dim3 grid(W / TW, H / TH, N);
    bilateral_kernel<<<grid, block>>>(img, params, outp);
}

// round 12
// speedup vs baseline: 1.1207x; 1.1207x over previous
#include <cuda_runtime.h>

// OriginNoiseBilateral R12: 17x17 bilateral, 8x3x512x512 fp32 NCHW.
// R8's winning machinery (grid-launched, packed f32x2 pairs, float4 halo
// tile, smem dym row table, lb(256,3)) widened to V=6 outputs/thread as 3
// packed pairs: each tap's LDS.128 + FFMA-imm + pack-MOV overhead is shared
// across 3 weight chains (-10% issue slots, -27% LDS per output). TH=48
// needs grid.y=11 and a store guard (512 % 48 != 0).

namespace {
constexpr int H = 512, W = 512, C = 3;
constexpr int HW = H * W;
constexpr int RMAX = 8;
constexpr int BX = 32, BY = 8;        // 256 threads
constexpr int V  = 6;                 // vertical outputs per thread (3 pairs)
constexpr int NP = 3;                 // pairs
constexpr int TW = BX;                // 32-wide output tile
constexpr int TH = BY * V;            // 48-tall output tile
constexpr int SW = TW + 2 * RMAX;     // 48
constexpr int SH = TH + 2 * RMAX;     // 64
constexpr int NTAP = 2 * RMAX + 1;    // 17
constexpr int NROW = V + 2 * RMAX;    // 22
constexpr int GY = (H + TH - 1) / TH; // 11 tiles vertically
constexpr float NEG_BIG = -1e30f;
constexpr float LOG2E = 1.4426950408889634f;
}

typedef unsigned long long u64;

__device__ __forceinline__ float ex2f(float x) {
    float y;
    asm("ex2.approx.ftz.f32 %0, %1;" : "=f"(y) : "f"(x));
    return y;
}
__device__ __forceinline__ u64 pack2(float lo, float hi) {
    u64 r;
    asm("mov.b64 %0, {%1, %2};" : "=l"(r) : "f"(lo), "f"(hi));
    return r;
}
__device__ __forceinline__ void unpack2(u64 v, float& lo, float& hi) {
    asm("mov.b64 {%0, %1}, %2;" : "=f"(lo), "=f"(hi) : "l"(v));
}
__device__ __forceinline__ u64 fma2(u64 a, u64 b, u64 c) {
    u64 d;
    asm("fma.rn.f32x2 %0, %1, %2, %3;" : "=l"(d) : "l"(a), "l"(b), "l"(c));
    return d;
}
__device__ __forceinline__ u64 add2(u64 a, u64 b) {
    u64 d;
    asm("add.rn.f32x2 %0, %1, %2;" : "=l"(d) : "l"(a), "l"(b));
    return d;
}

struct St3 {
    u64 ccx[NP], ccy[NP], ccz[NP];   // packed A-scaled center rgb per pair
    u64 nx[NP], ny[NP], nz[NP], dn[NP];
};

__device__ __forceinline__ void pair_tap(u64 sx2, u64 sy2, u64 sz2, u64 sw22,
                                         u64 rb, u64 ccx, u64 ccy, u64 ccz,
                                         u64& nx, u64& ny, u64& nz, u64& dn)
{
    u64 arg = fma2(sz2, ccz, fma2(sy2, ccy, fma2(sx2, ccx, add2(sw22, rb))));
    float a0, a1; unpack2(arg, a0, a1);
    u64 w2 = pack2(ex2f(a0), ex2f(a1));
    nx = fma2(w2, sx2, nx);
    ny = fma2(w2, sy2, ny);
    nz = fma2(w2, sz2, nz);
    dn = add2(dn, w2);
}

// One halo row; dx^2 terms are compile-time FFMA immediates; the tap's
// LDS.128 + FFMA-imm + packs are shared across all active pairs.
template<bool P0, bool P1, bool P2>
__device__ __forceinline__ void process_row(const float4* __restrict__ row,
                                            float m /* -inv2s */,
                                            u64 rb0, u64 rb1, u64 rb2, St3& st)
{
    #pragma unroll
    for (int dx = 0; dx < NTAP; dx++) {
        float4 s = row[dx];
        const float d2 = (float)((dx - RMAX) * (dx - RMAX));
        float sw2 = fmaf(d2, m, s.w);          // FFMA-imm (rt=1)
        u64 sw22 = pack2(sw2, sw2);
        u64 sx2  = pack2(s.x, s.x);
        u64 sy2  = pack2(s.y, s.y);
        u64 sz2  = pack2(s.z, s.z);
        if (P0) pair_tap(sx2, sy2, sz2, sw22, rb0, st.ccx[0], st.ccy[0], st.ccz[0],
                         st.nx[0], st.ny[0], st.nz[0], st.dn[0]);
        if (P1) pair_tap(sx2, sy2, sz2, sw22, rb1, st.ccx[1], st.ccy[1], st.ccz[1],
                         st.nx[1], st.ny[1], st.nz[1], st.dn[1]);
        if (P2) pair_tap(sx2, sy2, sz2, sw22, rb2, st.ccx[2], st.ccy[2], st.ccz[2],
                         st.nx[2], st.ny[2], st.nz[2], st.dn[2]);
    }
}

__global__ __launch_bounds__(256, 3)
void bilateral_kernel(const float* __restrict__ img,
                      const float* __restrict__ params,
                      float* __restrict__ out)
{
    __shared__ float4 tile[SH * SW];             // 64*48*16 = 49152 B
    __shared__ float  dym[NROW][V];              // thread-invariant row terms

    const int n   = blockIdx.z;
    const int tx  = threadIdx.x;
    const int ty  = threadIdx.y;
    const int tid = ty * BX + tx;

    const int x0 = blockIdx.x * TW - RMAX;
    const int y0 = blockIdx.y * TH - RMAX;

    const float* im = img + (size_t)n * C * HW;

    const int radius = ((((int)params[n * 3 + 0]) * 14 + 3) - 1) >> 1;
    const int r = radius < RMAX ? radius : RMAX;
    const float p1 = params[n * 3 + 1];
    const float p2 = params[n * 3 + 2];
    const float sc = fmaf(p1, 99.0f, 1.0f);
    const float ss = fmaf(p2, 99.0f, 1.0f);
    // 255^2 (reference pixel scaling) and log2(e) folded into constants.
    const float inv2c = 65025.0f * LOG2E / (2.0f * sc * sc);
    const float inv2s = LOG2E / (2.0f * ss * ss);
    const float m = -inv2s;
    const float A = 2.0f * inv2c;

    // Thread-invariant per-(row, v) spatial terms: dy^2*m, NEG_BIG if |dy|>8.
    if (tid < NROW * V) {
        int i = tid / V, v = tid - i * V;
        int dy = i - RMAX - v;
        dym[i][v] = (dy >= -RMAX && dy <= RMAX)
                  ? ((float)(dy * dy)) * m : NEG_BIG;
    }

    // Halo load with edge clamp; .w = -inv2c * |rgb|^2.
    #pragma unroll
    for (int i = tid; i < SH * SW; i += BX * BY) {
        int sy = i / SW, sx = i % SW;
        int gy = min(max(y0 + sy, 0), H - 1);
        int gx = min(max(x0 + sx, 0), W - 1);
        int b  = gy * W + gx;
        float a0 = im[b], a1 = im[b + HW], a2 = im[b + 2 * HW];
        float sq = fmaf(a2, a2, fmaf(a1, a1, a0 * a0));
        tile[i] = make_float4(a0, a1, a2, -inv2c * sq);
    }
    __syncthreads();

    float* obase = out + (size_t)n * C * HW + blockIdx.x * TW + tx;
    const int oy0 = blockIdx.y * TH + ty * V;

    if (r == RMAX) {
        // ---------------- Hot path ----------------
        St3 st;
        u64 cw[NP];
        #pragma unroll
        for (int p = 0; p < NP; p++) {
            float4 cA = tile[(ty * V + 2*p     + RMAX) * SW + (tx + RMAX)];
            float4 cB = tile[(ty * V + 2*p + 1 + RMAX) * SW + (tx + RMAX)];
            st.ccx[p] = pack2(A * cA.x, A * cB.x);
            st.ccy[p] = pack2(A * cA.y, A * cB.y);
            st.ccz[p] = pack2(A * cA.z, A * cB.z);
            st.nx[p] = st.ny[p] = st.nz[p] = st.dn[p] = pack2(0.0f, 0.0f);
            cw[p] = pack2(cA.w, cB.w);
        }

        const float4* row = &tile[(ty * V) * SW + tx];

        // Pair p active for i in [2p, 2p+17].
        #pragma unroll
        for (int i = 0; i < 2; i++) {          // P0 only
            u64 rb0 = add2(cw[0], *(const u64*)&dym[i][0]);
            process_row<true, false, false>(row, m, rb0, 0, 0, st);
            row += SW;
        }
        #pragma unroll
        for (int i = 2; i < 4; i++) {          // P0 P1
            u64 rb0 = add2(cw[0], *(const u64*)&dym[i][0]);
            u64 rb1 = add2(cw[1], *(const u64*)&dym[i][2]);
            process_row<true, true, false>(row, m, rb0, rb1, 0, st);
            row += SW;
        }
        #pragma unroll 2
        for (int i = 4; i < 18; i++) {         // all three pairs (hot body)
            u64 rb0 = add2(cw[0], *(const u64*)&dym[i][0]);
            u64 rb1 = add2(cw[1], *(const u64*)&dym[i][2]);
            u64 rb2 = add2(cw[2], *(const u64*)&dym[i][4]);
            process_row<true, true, true>(row, m, rb0, rb1, rb2, st);
            row += SW;
        }
        #pragma unroll
        for (int i = 18; i < 20; i++) {        // P1 P2
            u64 rb1 = add2(cw[1], *(const u64*)&dym[i][2]);
            u64 rb2 = add2(cw[2], *(const u64*)&dym[i][4]);
            process_row<false, true, true>(row, m, 0, rb1, rb2, st);
            row += SW;
        }
        #pragma unroll
        for (int i = 20; i < NROW; i++) {      // P2 only
            u64 rb2 = add2(cw[2], *(const u64*)&dym[i][4]);
            process_row<false, false, true>(row, m, 0, 0, rb2, st);
            row += SW;
        }

        #pragma unroll
        for (int p = 0; p < NP; p++) {
            float nxl, nxh, nyl, nyh, nzl, nzh, dl, dh;
            unpack2(st.nx[p], nxl, nxh);
            unpack2(st.ny[p], nyl, nyh);
            unpack2(st.nz[p], nzl, nzh);
            unpack2(st.dn[p], dl, dh);
            float il = __fdividef(1.0f, dl);
            float ih = __fdividef(1.0f, dh);
            int oyA = oy0 + 2*p, oyB = oy0 + 2*p + 1;
            if (oyA < H) {
                float* o0 = obase + oyA * W;
                o0[0] = nxl * il;  o0[HW] = nyl * il;  o0[2*HW] = nzl * il;
            }
            if (oyB < H) {
                float* o1 = obase + oyB * W;
                o1[0] = nxh * ih;  o1[HW] = nyh * ih;  o1[2*HW] = nzh * ih;
            }
        }
    } else {
        // ---------------- Cold generic path (radius < 8) ----------------
        #pragma unroll 1
        for (int v = 0; v < V; v++) {
            const int oy = oy0 + v;
            if (oy >= H) break;
            const float4 c = tile[(ty * V + v + RMAX) * SW + (tx + RMAX)];
            float n0 = 0.0f, n1 = 0.0f, n2 = 0.0f, den = 0.0f;
            #pragma unroll 1
            for (int dy = -r; dy <= r; dy++) {
                const float4* grow = &tile[(ty * V + v + RMAX + dy) * SW + (tx + RMAX)];
                const float spy = (float)(dy * dy);
                #pragma unroll 1
                for (int dx = -r; dx <= r; dx++) {
                    float4 s = grow[dx];
                    float tt = fmaf(s.z, c.z, fmaf(s.y, c.y, s.x * c.x));
                    float sp2 = spy + (float)(dx * dx);
                    float arg = fmaf(tt, A, fmaf(sp2, m, s.w + c.w));
                    float w = ex2f(arg);
                    n0 = fmaf(w, s.x, n0);
                    n1 = fmaf(w, s.y, n1);
                    n2 = fmaf(w, s.z, n2);
                    den += w;
                }
            }
            float inv = __fdividef(1.0f, den);
            float* o = obase + oy * W;
            o[0] = n0 * inv;  o[HW] = n1 * inv;  o[2*HW] = n2 * inv;
        }
    }
}

extern "C" void kernel_launch(void* const* d_in, const int* in_sizes, int n_in,
                              void* d_out, int out_size) {
    const float* img    = (const float*)d_in[0];
    const float* params = (const float*)d_in[1];
    float*       outp   = (float*)d_out;
    const int N = in_sizes[1] / 3;   // 8 images
    dim3 block(BX, BY, 1);
    dim3 grid(W / TW, GY, N);
    bilateral_kernel<<<grid, block>>>(img, params, outp);
}

// round 13
// speedup vs baseline: 1.1529x; 1.0288x over previous
#include <cuda_runtime.h>

// OriginNoiseBilateral R13: 17x17 bilateral, 8x3x512x512 fp32 NCHW.
// Byte-identical to R8's winning body (grid-launched, V=4 as 2 packed f32x2
// pairs, 48x48 float4 tile, smem dym row table) but at __launch_bounds__(256,2):
// ~128-reg budget -> ~90 scratch regs so ptxas can keep 5-6 arg->EX2->accum
// chains in flight per warp (R8's 80-reg/3-CTA config allowed ~2). Mid loop
// unrolled x4 now that the registers exist to materialize it.

namespace {
constexpr int H = 512, W = 512, C = 3;
constexpr int HW = H * W;
constexpr int RMAX = 8;
constexpr int BX = 32, BY = 8;        // 256 threads
constexpr int V  = 4;                 // vertical outputs per thread (2 pairs)
constexpr int TW = BX;                // 32-wide output tile
constexpr int TH = BY * V;            // 32-tall output tile
constexpr int SW = TW + 2 * RMAX;     // 48
constexpr int SH = TH + 2 * RMAX;     // 48
constexpr int NTAP = 2 * RMAX + 1;    // 17
constexpr int NROW = V + 2 * RMAX;    // 20
constexpr float NEG_BIG = -1e30f;
constexpr float LOG2E = 1.4426950408889634f;
}

typedef unsigned long long u64;

__device__ __forceinline__ float ex2f(float x) {
    float y;
    asm("ex2.approx.ftz.f32 %0, %1;" : "=f"(y) : "f"(x));
    return y;
}
__device__ __forceinline__ u64 pack2(float lo, float hi) {
    u64 r;
    asm("mov.b64 %0, {%1, %2};" : "=l"(r) : "f"(lo), "f"(hi));
    return r;
}
__device__ __forceinline__ void unpack2(u64 v, float& lo, float& hi) {
    asm("mov.b64 {%0, %1}, %2;" : "=f"(lo), "=f"(hi) : "l"(v));
}
__device__ __forceinline__ u64 fma2(u64 a, u64 b, u64 c) {
    u64 d;
    asm("fma.rn.f32x2 %0, %1, %2, %3;" : "=l"(d) : "l"(a), "l"(b), "l"(c));
    return d;
}
__device__ __forceinline__ u64 add2(u64 a, u64 b) {
    u64 d;
    asm("add.rn.f32x2 %0, %1, %2;" : "=l"(d) : "l"(a), "l"(b));
    return d;
}

struct PairState {
    u64 ccx[2], ccy[2], ccz[2];   // packed A-scaled center rgb per pair
    u64 nx[2], ny[2], nz[2], dn[2];
};

// One halo row. dx^2 terms are compile-time FFMA immediates.
template<bool P01, bool P23>
__device__ __forceinline__ void process_row(const float4* __restrict__ row,
                                            float m /* -inv2s */,
                                            u64 rb0, u64 rb1, PairState& st)
{
    #pragma unroll
    for (int dx = 0; dx < NTAP; dx++) {
        float4 s = row[dx];
        const float d2 = (float)((dx - RMAX) * (dx - RMAX));
        float sw2 = fmaf(d2, m, s.w);          // FFMA-imm (rt=1)
        u64 sw22 = pack2(sw2, sw2);
        u64 sx2  = pack2(s.x, s.x);
        u64 sy2  = pack2(s.y, s.y);
        u64 sz2  = pack2(s.z, s.z);
        if (P01) {
            u64 arg = fma2(sz2, st.ccz[0],
                      fma2(sy2, st.ccy[0],
                      fma2(sx2, st.ccx[0], add2(sw22, rb0))));
            float a0, a1; unpack2(arg, a0, a1);
            u64 w2 = pack2(ex2f(a0), ex2f(a1));
            st.nx[0] = fma2(w2, sx2, st.nx[0]);
            st.ny[0] = fma2(w2, sy2, st.ny[0]);
            st.nz[0] = fma2(w2, sz2, st.nz[0]);
            st.dn[0] = add2(st.dn[0], w2);
        }
        if (P23) {
            u64 arg = fma2(sz2, st.ccz[1],
                      fma2(sy2, st.ccy[1],
                      fma2(sx2, st.ccx[1], add2(sw22, rb1))));
            float a0, a1; unpack2(arg, a0, a1);
            u64 w2 = pack2(ex2f(a0), ex2f(a1));
            st.nx[1] = fma2(w2, sx2, st.nx[1]);
            st.ny[1] = fma2(w2, sy2, st.ny[1]);
            st.nz[1] = fma2(w2, sz2, st.nz[1]);
            st.dn[1] = add2(st.dn[1], w2);
        }
    }
}

__global__ __launch_bounds__(256, 2)
void bilateral_kernel(const float* __restrict__ img,
                      const float* __restrict__ params,
                      float* __restrict__ out)
{
    __shared__ float4 tile[SH * SW];             // 36864 B
    __shared__ float  dym[NROW][V];              // thread-invariant row terms

    const int n   = blockIdx.z;
    const int tx  = threadIdx.x;
    const int ty  = threadIdx.y;
    const int tid = ty * BX + tx;

    const int x0 = blockIdx.x * TW - RMAX;
    const int y0 = blockIdx.y * TH - RMAX;

    const float* im = img + (size_t)n * C * HW;

    const int radius = ((((int)params[n * 3 + 0]) * 14 + 3) - 1) >> 1;
    const int r = radius < RMAX ? radius : RMAX;
    const float p1 = params[n * 3 + 1];
    const float p2 = params[n * 3 + 2];
    const float sc = fmaf(p1, 99.0f, 1.0f);
    const float ss = fmaf(p2, 99.0f, 1.0f);
    // 255^2 (reference pixel scaling) and log2(e) folded into constants.
    const float inv2c = 65025.0f * LOG2E / (2.0f * sc * sc);
    const float inv2s = LOG2E / (2.0f * ss * ss);
    const float m = -inv2s;
    const float A = 2.0f * inv2c;

    // Thread-invariant per-(row, v) spatial terms: dy^2*m, NEG_BIG if |dy|>8.
    if (tid < NROW * V) {
        int i = tid >> 2, v = tid & 3;
        int dy = i - RMAX - v;
        dym[i][v] = (dy >= -RMAX && dy <= RMAX)
                  ? ((float)(dy * dy)) * m : NEG_BIG;
    }

    // Halo load with edge clamp; .w = -inv2c * |rgb|^2.
    #pragma unroll
    for (int i = tid; i < SH * SW; i += BX * BY) {
        int sy = i / SW, sx = i % SW;
        int gy = min(max(y0 + sy, 0), H - 1);
        int gx = min(max(x0 + sx, 0), W - 1);
        int b  = gy * W + gx;
        float a0 = im[b], a1 = im[b + HW], a2 = im[b + 2 * HW];
        float sq = fmaf(a2, a2, fmaf(a1, a1, a0 * a0));
        tile[i] = make_float4(a0, a1, a2, -inv2c * sq);
    }
    __syncthreads();

    float* obase = out + (size_t)n * C * HW + blockIdx.x * TW + tx;
    const int oy0 = blockIdx.y * TH + ty * V;

    if (r == RMAX) {
        // ---------------- Hot path ----------------
        float4 cc[V];
        #pragma unroll
        for (int v = 0; v < V; v++)
            cc[v] = tile[(ty * V + v + RMAX) * SW + (tx + RMAX)];

        PairState st;
        #pragma unroll
        for (int p = 0; p < 2; p++) {
            st.ccx[p] = pack2(A * cc[2*p].x, A * cc[2*p+1].x);
            st.ccy[p] = pack2(A * cc[2*p].y, A * cc[2*p+1].y);
            st.ccz[p] = pack2(A * cc[2*p].z, A * cc[2*p+1].z);
            st.nx[p] = st.ny[p] = st.nz[p] = st.dn[p] = pack2(0.0f, 0.0f);
        }
        const u64 cw01 = pack2(cc[0].w, cc[1].w);
        const u64 cw23 = pack2(cc[2].w, cc[3].w);

        const float4* row = &tile[(ty * V) * SW + tx];

        // Head rows: only pair01 active (i = 0, 1).
        #pragma unroll
        for (int i = 0; i < 2; i++) {
            u64 rb0 = add2(cw01, *(const u64*)&dym[i][0]);
            process_row<true, false>(row, m, rb0, 0, st);
            row += SW;
        }
        // Mid rows: both pairs (i = 2..17), unrolled x4 (regs now allow it).
        #pragma unroll 4
        for (int i = 2; i < 2 * RMAX + 2; i++) {
            u64 rb0 = add2(cw01, *(const u64*)&dym[i][0]);
            u64 rb1 = add2(cw23, *(const u64*)&dym[i][2]);
            process_row<true, true>(row, m, rb0, rb1, st);
            row += SW;
        }
        // Tail rows: only pair23 active (i = 18, 19).
        #pragma unroll
        for (int i = 2 * RMAX + 2; i < NROW; i++) {
            u64 rb1 = add2(cw23, *(const u64*)&dym[i][2]);
            process_row<false, true>(row, m, 0, rb1, st);
            row += SW;
        }

        #pragma unroll
        for (int p = 0; p < 2; p++) {
            float nxl, nxh, nyl, nyh, nzl, nzh, dl, dh;
            unpack2(st.nx[p], nxl, nxh);
            unpack2(st.ny[p], nyl, nyh);
            unpack2(st.nz[p], nzl, nzh);
            unpack2(st.dn[p], dl, dh);
            float il = __fdividef(1.0f, dl);
            float ih = __fdividef(1.0f, dh);
            float* o0 = obase + (oy0 + 2*p) * W;
            float* o1 = obase + (oy0 + 2*p + 1) * W;
            o0[0] = nxl * il;  o0[HW] = nyl * il;  o0[2*HW] = nzl * il;
            o1[0] = nxh * ih;  o1[HW] = nyh * ih;  o1[2*HW] = nzh * ih;
        }
    } else {
        // ---------------- Cold generic path (radius < 8) ----------------
        #pragma unroll 1
        for (int v = 0; v < V; v++) {
            const float4 c = tile[(ty * V + v + RMAX) * SW + (tx + RMAX)];
            float n0 = 0.0f, n1 = 0.0f, n2 = 0.0f, den = 0.0f;
            #pragma unroll 1
            for (int dy = -r; dy <= r; dy++) {
                const float4* grow = &tile[(ty * V + v + RMAX + dy) * SW + (tx + RMAX)];
                const float spy = (float)(dy * dy);
                #pragma unroll 1
                for (int dx = -r; dx <= r; dx++) {
                    float4 s = grow[dx];
                    float tt = fmaf(s.z, c.z, fmaf(s.y, c.y, s.x * c.x));
                    float sp2 = spy + (float)(dx * dx);
                    float arg = fmaf(tt, A, fmaf(sp2, m, s.w + c.w));
                    float w = ex2f(arg);
                    n0 = fmaf(w, s.x, n0);
                    n1 = fmaf(w, s.y, n1);
                    n2 = fmaf(w, s.z, n2);
                    den += w;
                }
            }
            float inv = __fdividef(1.0f, den);
            float* o = obase + (oy0 + v) * W;
            o[0] = n0 * inv;  o[HW] = n1 * inv;  o[2*HW] = n2 * inv;
        }
    }
}

extern "C" void kernel_launch(void* const* d_in, const int* in_sizes, int n_in,
                              void* d_out, int out_size) {
    const float* img    = (const float*)d_in[0];
    const float* params = (const float*)d_in[1];
    float*       outp   = (float*)d_out;
    const int N = in_sizes[1] / 3;   // 8 images
    dim3 block(BX, BY, 1);
    dim3 grid(W / TW, H / TH, N);
    bilateral_kernel<<<grid, block>>>(img, params, outp);
}

// round 14
// speedup vs baseline: 1.1636x; 1.0092x over previous
#include <cuda_runtime.h>

// OriginNoiseBilateral R14 (converged): 17x17 bilateral, 8x3x512x512 fp32 NCHW.
// R8 optimum: grid-launched, V=4 outputs/thread as 2 packed f32x2 pairs,
// 48x48 float4 halo tile, thread-invariant dy^2 smem table, lb(256,3),
// mid-row unroll x2. Model: 8-packed-op core = 22 SMSP-cyc/pair-tap under
// RF-banking (FFMA2 w/ 3 distinct u64 operands -> rt=3); measured 24 cyc =
// 92-98% of that floor; fma busy 70% == predicted 16.8/24. All alternative
// formulations (scalar, squaring, taps-in-lanes, plane-duplication, poly
// exp2, fp16 exp, symmetric weights) enumerated and dominated.
// R14 micro: halo-loop index div/mod replaced by incremental carry stepping.

namespace {
constexpr int H = 512, W = 512, C = 3;
constexpr int HW = H * W;
constexpr int RMAX = 8;
constexpr int BX = 32, BY = 8;        // 256 threads
constexpr int V  = 4;                 // vertical outputs per thread (2 pairs)
constexpr int TW = BX;                // 32-wide output tile
constexpr int TH = BY * V;            // 32-tall output tile
constexpr int SW = TW + 2 * RMAX;     // 48
constexpr int SH = TH + 2 * RMAX;     // 48
constexpr int NTAP = 2 * RMAX + 1;    // 17
constexpr int NROW = V + 2 * RMAX;    // 20
constexpr float NEG_BIG = -1e30f;
constexpr float LOG2E = 1.4426950408889634f;
}

typedef unsigned long long u64;

__device__ __forceinline__ float ex2f(float x) {
    float y;
    asm("ex2.approx.ftz.f32 %0, %1;" : "=f"(y) : "f"(x));
    return y;
}
__device__ __forceinline__ u64 pack2(float lo, float hi) {
    u64 r;
    asm("mov.b64 %0, {%1, %2};" : "=l"(r) : "f"(lo), "f"(hi));
    return r;
}
__device__ __forceinline__ void unpack2(u64 v, float& lo, float& hi) {
    asm("mov.b64 {%0, %1}, %2;" : "=f"(lo), "=f"(hi) : "l"(v));
}
__device__ __forceinline__ u64 fma2(u64 a, u64 b, u64 c) {
    u64 d;
    asm("fma.rn.f32x2 %0, %1, %2, %3;" : "=l"(d) : "l"(a), "l"(b), "l"(c));
    return d;
}
__device__ __forceinline__ u64 add2(u64 a, u64 b) {
    u64 d;
    asm("add.rn.f32x2 %0, %1, %2;" : "=l"(d) : "l"(a), "l"(b));
    return d;
}

struct PairState {
    u64 ccx[2], ccy[2], ccz[2];   // packed A-scaled center rgb per pair
    u64 nx[2], ny[2], nz[2], dn[2];
};

// One halo row. dx^2 terms are compile-time FFMA immediates.
template<bool P01, bool P23>
__device__ __forceinline__ void process_row(const float4* __restrict__ row,
                                            float m /* -inv2s */,
                                            u64 rb0, u64 rb1, PairState& st)
{
    #pragma unroll
    for (int dx = 0; dx < NTAP; dx++) {
        float4 s = row[dx];
        const float d2 = (float)((dx - RMAX) * (dx - RMAX));
        float sw2 = fmaf(d2, m, s.w);          // FFMA-imm (rt=1)
        u64 sw22 = pack2(sw2, sw2);
        u64 sx2  = pack2(s.x, s.x);
        u64 sy2  = pack2(s.y, s.y);
        u64 sz2  = pack2(s.z, s.z);
        if (P01) {
            u64 arg = fma2(sz2, st.ccz[0],
                      fma2(sy2, st.ccy[0],
                      fma2(sx2, st.ccx[0], add2(sw22, rb0))));
            float a0, a1; unpack2(arg, a0, a1);
            u64 w2 = pack2(ex2f(a0), ex2f(a1));
            st.nx[0] = fma2(w2, sx2, st.nx[0]);
            st.ny[0] = fma2(w2, sy2, st.ny[0]);
            st.nz[0] = fma2(w2, sz2, st.nz[0]);
            st.dn[0] = add2(st.dn[0], w2);
        }
        if (P23) {
            u64 arg = fma2(sz2, st.ccz[1],
                      fma2(sy2, st.ccy[1],
                      fma2(sx2, st.ccx[1], add2(sw22, rb1))));
            float a0, a1; unpack2(arg, a0, a1);
            u64 w2 = pack2(ex2f(a0), ex2f(a1));
            st.nx[1] = fma2(w2, sx2, st.nx[1]);
            st.ny[1] = fma2(w2, sy2, st.ny[1]);
            st.nz[1] = fma2(w2, sz2, st.nz[1]);
            st.dn[1] = add2(st.dn[1], w2);
        }
    }
}

__global__ __launch_bounds__(256, 3)
void bilateral_kernel(const float* __restrict__ img,
                      const float* __restrict__ params,
                      float* __restrict__ out)
{
    __shared__ float4 tile[SH * SW];             // 36864 B
    __shared__ float  dym[NROW][V];              // thread-invariant row terms

    const int n   = blockIdx.z;
    const int tx  = threadIdx.x;
    const int ty  = threadIdx.y;
    const int tid = ty * BX + tx;

    const int x0 = blockIdx.x * TW - RMAX;
    const int y0 = blockIdx.y * TH - RMAX;

    const float* im = img + (size_t)n * C * HW;

    const int radius = ((((int)params[n * 3 + 0]) * 14 + 3) - 1) >> 1;
    const int r = radius < RMAX ? radius : RMAX;
    const float p1 = params[n * 3 + 1];
    const float p2 = params[n * 3 + 2];
    const float sc = fmaf(p1, 99.0f, 1.0f);
    const float ss = fmaf(p2, 99.0f, 1.0f);
    // 255^2 (reference pixel scaling) and log2(e) folded into constants.
    const float inv2c = 65025.0f * LOG2E / (2.0f * sc * sc);
    const float inv2s = LOG2E / (2.0f * ss * ss);
    const float m = -inv2s;
    const float A = 2.0f * inv2c;

    // Thread-invariant per-(row, v) spatial terms: dy^2*m, NEG_BIG if |dy|>8.
    if (tid < NROW * V) {
        int i = tid >> 2, v = tid & 3;
        int dy = i - RMAX - v;
        dym[i][v] = (dy >= -RMAX && dy <= RMAX)
                  ? ((float)(dy * dy)) * m : NEG_BIG;
    }

    // Halo load with edge clamp; .w = -inv2c * |rgb|^2.
    // Incremental (sy, sx) stepping: 256 = 5*48 + 16 (no div/mod per iter).
    {
        int sy = tid / SW, sx = tid - sy * SW;
        #pragma unroll
        for (int it = 0; it < (SH * SW + BX * BY - 1) / (BX * BY); it++) {
            int idx = sy * SW + sx;
            if (idx < SH * SW) {
                int gy = min(max(y0 + sy, 0), H - 1);
                int gx = min(max(x0 + sx, 0), W - 1);
                int b  = gy * W + gx;
                float a0 = im[b], a1 = im[b + HW], a2 = im[b + 2 * HW];
                float sq = fmaf(a2, a2, fmaf(a1, a1, a0 * a0));
                tile[idx] = make_float4(a0, a1, a2, -inv2c * sq);
            }
            sy += 5; sx += 16;
            if (sx >= SW) { sx -= SW; sy += 1; }
        }
    }
    __syncthreads();

    float* obase = out + (size_t)n * C * HW + blockIdx.x * TW + tx;
    const int oy0 = blockIdx.y * TH + ty * V;

    if (r == RMAX) {
        // ---------------- Hot path ----------------
        float4 cc[V];
        #pragma unroll
        for (int v = 0; v < V; v++)
            cc[v] = tile[(ty * V + v + RMAX) * SW + (tx + RMAX)];

        PairState st;
        #pragma unroll
        for (int p = 0; p < 2; p++) {
            st.ccx[p] = pack2(A * cc[2*p].x, A * cc[2*p+1].x);
            st.ccy[p] = pack2(A * cc[2*p].y, A * cc[2*p+1].y);
            st.ccz[p] = pack2(A * cc[2*p].z, A * cc[2*p+1].z);
            st.nx[p] = st.ny[p] = st.nz[p] = st.dn[p] = pack2(0.0f, 0.0f);
        }
        const u64 cw01 = pack2(cc[0].w, cc[1].w);
        const u64 cw23 = pack2(cc[2].w, cc[3].w);

        const float4* row = &tile[(ty * V) * SW + tx];

        // Head rows: only pair01 active (i = 0, 1).
        #pragma unroll
        for (int i = 0; i < 2; i++) {
            u64 rb0 = add2(cw01, *(const u64*)&dym[i][0]);
            process_row<true, false>(row, m, rb0, 0, st);
            row += SW;
        }
        // Mid rows: both pairs (i = 2..17).
        #pragma unroll 2
        for (int i = 2; i < 2 * RMAX + 2; i++) {
            u64 rb0 = add2(cw01, *(const u64*)&dym[i][0]);
            u64 rb1 = add2(cw23, *(const u64*)&dym[i][2]);
            process_row<true, true>(row, m, rb0, rb1, st);
            row += SW;
        }
        // Tail rows: only pair23 active (i = 18, 19).
        #pragma unroll
        for (int i = 2 * RMAX + 2; i < NROW; i++) {
            u64 rb1 = add2(cw23, *(const u64*)&dym[i][2]);
            process_row<false, true>(row, m, 0, rb1, st);
            row += SW;
        }

        #pragma unroll
        for (int p = 0; p < 2; p++) {
            float nxl, nxh, nyl, nyh, nzl, nzh, dl, dh;
            unpack2(st.nx[p], nxl, nxh);
            unpack2(st.ny[p], nyl, nyh);
            unpack2(st.nz[p], nzl, nzh);
            unpack2(st.dn[p], dl, dh);
            float il = __fdividef(1.0f, dl);
            float ih = __fdividef(1.0f, dh);
            float* o0 = obase + (oy0 + 2*p) * W;
            float* o1 = obase + (oy0 + 2*p + 1) * W;
            o0[0] = nxl * il;  o0[HW] = nyl * il;  o0[2*HW] = nzl * il;
            o1[0] = nxh * ih;  o1[HW] = nyh * ih;  o1[2*HW] = nzh * ih;
        }
    } else {
        // ---------------- Cold generic path (radius < 8) ----------------
        #pragma unroll 1
        for (int v = 0; v < V; v++) {
            const float4 c = tile[(ty * V + v + RMAX) * SW + (tx + RMAX)];
            float n0 = 0.0f, n1 = 0.0f, n2 = 0.0f, den = 0.0f;
            #pragma unroll 1
            for (int dy = -r; dy <= r; dy++) {
                const float4* grow = &tile[(ty * V + v + RMAX + dy) * SW + (tx + RMAX)];
                const float spy = (float)(dy * dy);
                #pragma unroll 1
                for (int dx = -r; dx <= r; dx++) {
                    float4 s = grow[dx];
                    float tt = fmaf(s.z, c.z, fmaf(s.y, c.y, s.x * c.x));
                    float sp2 = spy + (float)(dx * dx);
                    float arg = fmaf(tt, A, fmaf(sp2, m, s.w + c.w));
                    float w = ex2f(arg);
                    n0 = fmaf(w, s.x, n0);
                    n1 = fmaf(w, s.y, n1);
                    n2 = fmaf(w, s.z, n2);
                    den += w;
                }
            }
            float inv = __fdividef(1.0f, den);
            float* o = obase + (oy0 + v) * W;
            o[0] = n0 * inv;  o[HW] = n1 * inv;  o[2*HW] = n2 * inv;
        }
    }
}

extern "C" void kernel_launch(void* const* d_in, const int* in_sizes, int n_in,
                              void* d_out, int out_size) {
    const float* img    = (const float*)d_in[0];
    const float* params = (const float*)d_in[1];
    float*       outp   = (float*)d_out;
    const int N = in_sizes[1] / 3;   // 8 images
    dim3 block(BX, BY, 1);
    dim3 grid(W / TW, H / TH, N);
    bilateral_kernel<<<grid, block>>>(img, params, outp);
}